// round 14
// baseline (speedup 1.0000x reference)
#include <cuda_runtime.h>

// IntraAgg, R14: TWO batch rows per warp, 16 lanes per row (lane owns 2
// float4 chunks: hl and hl+16). Every warp instruction now serves 2 rows:
//   - loads: 2 LDG.128 per neighbor cover both halves' rows (same 4
//     wavefronts/row as the 32-lane scheme)
//   - ranking reduction: 4 chunk-pairs of 8 neighbors; per chunk, 8-slot
//     transpose-reduce over 16 lanes (select-free xor-8 pre-stage + 3
//     halving stages) -> lane hl gets dot/norm of neighbor 8c+(hl&7)
//   - selection: lane hl owns neighbors hl (a) and 16+hl (b); one REDUX
//     loop with per-half masks picks top-ns for both rows at once;
//     a-before-b + lowest-lane = ascending-index tie-break (lax.top_k)
//   - phase 3 + epilogue in packed f32x2
// Per-row issue slots ~850 -> ~535; L1/L2 bytes per row unchanged.

#define FULLM 0xffffffffu
#define K_NEIGH 32

typedef unsigned long long u64;

static __device__ __forceinline__ u64 pk2(float lo, float hi) {
    u64 r; asm("mov.b64 %0, {%1, %2};" : "=l"(r) : "f"(lo), "f"(hi)); return r;
}
static __device__ __forceinline__ void upk2(float& lo, float& hi, u64 v) {
    asm("mov.b64 {%0, %1}, %2;" : "=f"(lo), "=f"(hi) : "l"(v));
}
static __device__ __forceinline__ u64 mul2(u64 a, u64 b) {
    u64 d; asm("mul.rn.f32x2 %0, %1, %2;" : "=l"(d) : "l"(a), "l"(b)); return d;
}
static __device__ __forceinline__ u64 fma2(u64 a, u64 b, u64 c) {
    u64 d; asm("fma.rn.f32x2 %0, %1, %2, %3;" : "=l"(d) : "l"(a), "l"(b), "l"(c)); return d;
}
static __device__ __forceinline__ u64 add2(u64 a, u64 b) {
    u64 d; asm("add.rn.f32x2 %0, %1, %2;" : "=l"(d) : "l"(a), "l"(b)); return d;
}

__global__ __launch_bounds__(128)
void intra_agg_kernel(const float* __restrict__ features,
                      const int*   __restrict__ nodes,
                      const int*   __restrict__ neighs,
                      const int*   __restrict__ nsp,   // may be null
                      float*       __restrict__ out,
                      int B)
{
    const int gw   = (blockIdx.x * blockDim.x + threadIdx.x) >> 5;
    const int lane = threadIdx.x & 31;
    const int hl   = lane & 15;          // half-local lane
    const int half = lane >> 4;          // which row of the pair

    const int row0 = gw * 2;
    if (row0 >= B) return;               // warp-uniform exit
    int myRow = row0 + half;
    const bool wr = (myRow < B);
    if (!wr) myRow = row0;               // clamp: compute redundantly, no store

    int ns = (nsp != nullptr) ? __ldg(nsp) : 10;
    ns = min(max(ns, 1), K_NEIGH);

    const float4* __restrict__ f4   = reinterpret_cast<const float4*>(features);
    const int*    __restrict__ nrow = neighs + myRow * K_NEIGH;  // uniform per half
    const int4*   __restrict__ n4   = reinterpret_cast<const int4*>(nrow);

    const unsigned hm = half ? 0xFFFF0000u : 0x0000FFFFu;

    const int node = __ldg(&nodes[myRow]);
    const float4 cA = __ldg(&f4[node * 32 + hl]);
    const float4 cB = __ldg(&f4[node * 32 + 16 + hl]);
    const u64 cAa = pk2(cA.x, cA.y), cAb = pk2(cA.z, cA.w);
    const u64 cBa = pk2(cB.x, cB.y), cBb = pk2(cB.z, cB.w);

    // ---------------- Phase 1: ranking scores ------------------------------
    // s[c] = score of neighbor 8c + (hl&7)  (duplicated across the two
    // 8-lane subgroups of each half; resolved below).
    float s[4];
    #pragma unroll
    for (int ch = 0; ch < 4; ++ch) {
        const int4 qa = __ldg(&n4[ch * 2]);
        const int4 qb = __ldg(&n4[ch * 2 + 1]);
        const int r[8] = {qa.x, qa.y, qa.z, qa.w, qb.x, qb.y, qb.z, qb.w};
        float pd[8], pn[8];
        #pragma unroll
        for (int j0 = 0; j0 < 8; j0 += 2) {       // batch 2 neighbors (4 LDG)
            const float4 v0A = __ldg(&f4[r[j0]     * 32 + hl]);
            const float4 v0B = __ldg(&f4[r[j0]     * 32 + 16 + hl]);
            const float4 v1A = __ldg(&f4[r[j0 + 1] * 32 + hl]);
            const float4 v1B = __ldg(&f4[r[j0 + 1] * 32 + 16 + hl]);
            {
                const u64 xa = pk2(v0A.x, v0A.y), xb = pk2(v0A.z, v0A.w);
                const u64 ya = pk2(v0B.x, v0B.y), yb = pk2(v0B.z, v0B.w);
                u64 d2 = mul2(xa, cAa); d2 = fma2(xb, cAb, d2);
                d2 = fma2(ya, cBa, d2); d2 = fma2(yb, cBb, d2);
                u64 n2 = mul2(xa, xa);  n2 = fma2(xb, xb, n2);
                n2 = fma2(ya, ya, n2);  n2 = fma2(yb, yb, n2);
                float a, b, c, d; upk2(a, b, d2); upk2(c, d, n2);
                pd[j0] = a + b; pn[j0] = c + d;
            }
            {
                const u64 xa = pk2(v1A.x, v1A.y), xb = pk2(v1A.z, v1A.w);
                const u64 ya = pk2(v1B.x, v1B.y), yb = pk2(v1B.z, v1B.w);
                u64 d2 = mul2(xa, cAa); d2 = fma2(xb, cAb, d2);
                d2 = fma2(ya, cBa, d2); d2 = fma2(yb, cBb, d2);
                u64 n2 = mul2(xa, xa);  n2 = fma2(xb, xb, n2);
                n2 = fma2(ya, ya, n2);  n2 = fma2(yb, yb, n2);
                float a, b, c, d; upk2(a, b, d2); upk2(c, d, n2);
                pd[j0 + 1] = a + b; pn[j0 + 1] = c + d;
            }
        }
        // select-free pre-stage: fold the two 8-lane subgroups of each half
        #pragma unroll
        for (int j = 0; j < 8; ++j) {
            pd[j] += __shfl_xor_sync(FULLM, pd[j], 8);
            pn[j] += __shfl_xor_sync(FULLM, pn[j], 8);
        }
        // 8-slot transpose reduce over xor {4,2,1}: lane gets slot (lane&7)
        #pragma unroll
        for (int o = 4; o >= 1; o >>= 1) {
            #pragma unroll
            for (int j = 0; j < o; ++j) {
                const float sd = (lane & o) ? pd[j] : pd[j + o];
                const float rd = __shfl_xor_sync(FULLM, sd, o);
                pd[j] = ((lane & o) ? pd[j + o] : pd[j]) + rd;
                const float sn = (lane & o) ? pn[j] : pn[j + o];
                const float rn = __shfl_xor_sync(FULLM, sn, o);
                pn[j] = ((lane & o) ? pn[j + o] : pn[j]) + rn;
            }
        }
        s[ch] = pd[0] * rsqrtf(pn[0]);   // cosine rank (c-norm drops out)
    }

    // Lane hl owns: a = neighbor hl, b = neighbor 16+hl.
    const bool hi8 = (hl & 8) != 0;
    const float sa = hi8 ? s[1] : s[0];
    const float sb = hi8 ? s[3] : s[2];
    unsigned ua = __float_as_uint(sa);
    ua = (ua & 0x80000000u) ? ~ua : (ua | 0x80000000u);
    unsigned ub = __float_as_uint(sb);
    ub = (ub & 0x80000000u) ? ~ub : (ub | 0x80000000u);

    // ---------------- Phase 2: top-ns over 32 candidates, per half ---------
    bool ea = false, eb = false;
    for (int i = 0; i < ns; ++i) {
        const unsigned va = ea ? 0u : ua;
        const unsigned vb = eb ? 0u : ub;
        const unsigned w  = va > vb ? va : vb;
        const unsigned m  = __reduce_max_sync(hm, w);
        const unsigned ba = __ballot_sync(hm, va == m);
        const unsigned bb = __ballot_sync(hm, vb == m);
        const bool isA = (ba != 0u);                  // a-side (idx<16) first
        const unsigned bs = isA ? ba : bb;
        const int wl = __ffs(bs) - 1;                 // lowest lane on ties
        ea = ea || ( isA && lane == wl);
        eb = eb || (!isA && lane == wl);
    }
    const unsigned bAsel = __ballot_sync(hm, ea);
    const unsigned bBsel = __ballot_sync(hm, eb);
    const unsigned sh = half * 16;
    const unsigned sel32 = ((bAsel >> sh) & 0xFFFFu)
                         | (((bBsel >> sh) & 0xFFFFu) << 16); // bit k = nbr k

    // ---------------- Phase 3: mean of selected rows + relu ----------------
    u64 accA = pk2(0.f, 0.f), accB = pk2(0.f, 0.f);
    u64 accC = pk2(0.f, 0.f), accD = pk2(0.f, 0.f);
    if (ns == 10) {
        int kk[10];
        unsigned rem = sel32;
        #pragma unroll
        for (int i = 0; i < 10; ++i) { kk[i] = __ffs(rem) - 1; rem &= rem - 1; }
        int rI[10];
        #pragma unroll
        for (int i = 0; i < 10; ++i) rI[i] = __ldg(&nrow[kk[i]]);
        #pragma unroll
        for (int i0 = 0; i0 < 10; i0 += 2) {
            const float4 u0 = __ldg(&f4[rI[i0]     * 32 + hl]);
            const float4 u1 = __ldg(&f4[rI[i0]     * 32 + 16 + hl]);
            const float4 w0 = __ldg(&f4[rI[i0 + 1] * 32 + hl]);
            const float4 w1 = __ldg(&f4[rI[i0 + 1] * 32 + 16 + hl]);
            accA = add2(accA, pk2(u0.x, u0.y)); accB = add2(accB, pk2(u0.z, u0.w));
            accC = add2(accC, pk2(u1.x, u1.y)); accD = add2(accD, pk2(u1.z, u1.w));
            accA = add2(accA, pk2(w0.x, w0.y)); accB = add2(accB, pk2(w0.z, w0.w));
            accC = add2(accC, pk2(w1.x, w1.y)); accD = add2(accD, pk2(w1.z, w1.w));
        }
    } else {
        unsigned rem = sel32;
        for (int i = 0; i < ns; ++i) {
            const int k = __ffs(rem) - 1;
            rem &= rem - 1;
            const int rI = __ldg(&nrow[k]);
            const float4 u0 = __ldg(&f4[rI * 32 + hl]);
            const float4 u1 = __ldg(&f4[rI * 32 + 16 + hl]);
            accA = add2(accA, pk2(u0.x, u0.y)); accB = add2(accB, pk2(u0.z, u0.w));
            accC = add2(accC, pk2(u1.x, u1.y)); accD = add2(accD, pk2(u1.z, u1.w));
        }
    }
    float ax, ay, az, aw, bx, by, bz, bw;
    upk2(ax, ay, accA); upk2(az, aw, accB);
    upk2(bx, by, accC); upk2(bz, bw, accD);
    const float inv = 1.0f / (float)ns;
    if (wr) {
        float4 o1, o2;
        o1.x = fmaxf(ax * inv, 0.0f); o1.y = fmaxf(ay * inv, 0.0f);
        o1.z = fmaxf(az * inv, 0.0f); o1.w = fmaxf(aw * inv, 0.0f);
        o2.x = fmaxf(bx * inv, 0.0f); o2.y = fmaxf(by * inv, 0.0f);
        o2.z = fmaxf(bz * inv, 0.0f); o2.w = fmaxf(bw * inv, 0.0f);
        float4* o4 = reinterpret_cast<float4*>(out);
        o4[myRow * 32 + hl]      = o1;
        o4[myRow * 32 + 16 + hl] = o2;
    }
}

extern "C" void kernel_launch(void* const* d_in, const int* in_sizes, int n_in,
                              void* d_out, int out_size)
{
    const float* features = (const float*)d_in[0];
    const int*   nodes    = (const int*)d_in[1];
    const int*   neighs   = (const int*)d_in[2];
    const int*   nsp      = (n_in > 3) ? (const int*)d_in[3] : nullptr;

    const int B = in_sizes[1];                 // nodes element count = batch
    const int threads = 128;                   // 4 warps = 8 rows per block
    const int rows_per_block = (threads / 32) * 2;
    const int grid = (B + rows_per_block - 1) / rows_per_block;

    intra_agg_kernel<<<grid, threads>>>(features, nodes, neighs, nsp,
                                        (float*)d_out, B);
}